// round 1
// baseline (speedup 1.0000x reference)
#include <cuda_runtime.h>
#include <cuda_bf16.h>

// Problem constants (fixed by the reference)
#define N_NODES 50000
#define N_EDGES 800000
#define NFEAT   512
#define NHID    128
#define NCLASS  40

// Device scratch (no cudaMalloc allowed)
__device__ float g_h1[N_NODES * NHID];    // support1 = x @ W1      (25.6 MB)
__device__ float g_agg1[N_NODES * NHID];  // aggregated layer-1 out (25.6 MB)
__device__ float g_h2[N_NODES * NCLASS];  // support2 = relu(h) @ W2 (8 MB)

// ---------------------------------------------------------------------------
// GEMM1: C[M,128] = A[M,512] @ B[512,128]   (fp32, tiled)
// BM=128, BN=128, BK=16, 256 threads, 8x8 micro-tile per thread
// ---------------------------------------------------------------------------
__global__ __launch_bounds__(256) void gemm1_kernel(
    const float* __restrict__ A, const float* __restrict__ B,
    float* __restrict__ C, int M)
{
    __shared__ float As[16][128];   // [k][m]
    __shared__ float Bs[16][128];   // [k][n]

    const int block_row = blockIdx.x * 128;
    const int tx = threadIdx.x & 15;        // 0..15 (n-direction)
    const int ty = threadIdx.x >> 4;        // 0..15 (m-direction)

    float acc[8][8];
#pragma unroll
    for (int i = 0; i < 8; i++)
#pragma unroll
        for (int j = 0; j < 8; j++) acc[i][j] = 0.0f;

    for (int k0 = 0; k0 < NFEAT; k0 += 16) {
        // Load A tile: 128 rows x 16 k = 512 float4, 2 per thread
#pragma unroll
        for (int it = 0; it < 2; it++) {
            int lin = threadIdx.x + it * 256;    // float4 index 0..511
            int r   = lin >> 2;                  // row in tile (4 f4 per row)
            int kk  = (lin & 3) * 4;
            int grow = block_row + r;
            float4 v = make_float4(0.f, 0.f, 0.f, 0.f);
            if (grow < M) v = *(const float4*)&A[(size_t)grow * NFEAT + k0 + kk];
            As[kk + 0][r] = v.x; As[kk + 1][r] = v.y;
            As[kk + 2][r] = v.z; As[kk + 3][r] = v.w;
        }
        // Load B tile: 16 rows x 128 cols = 512 float4, 2 per thread
#pragma unroll
        for (int it = 0; it < 2; it++) {
            int lin = threadIdx.x + it * 256;
            int r   = lin >> 5;                  // 32 f4 per row
            int cc  = (lin & 31) * 4;
            float4 v = *(const float4*)&B[(size_t)(k0 + r) * NHID + cc];
            *(float4*)&Bs[r][cc] = v;
        }
        __syncthreads();

#pragma unroll
        for (int k = 0; k < 16; k++) {
            float a[8], b[8];
            *(float4*)&a[0] = *(const float4*)&As[k][ty * 8];
            *(float4*)&a[4] = *(const float4*)&As[k][ty * 8 + 4];
            *(float4*)&b[0] = *(const float4*)&Bs[k][tx * 8];
            *(float4*)&b[4] = *(const float4*)&Bs[k][tx * 8 + 4];
#pragma unroll
            for (int i = 0; i < 8; i++)
#pragma unroll
                for (int j = 0; j < 8; j++) acc[i][j] += a[i] * b[j];
        }
        __syncthreads();
    }

#pragma unroll
    for (int i = 0; i < 8; i++) {
        int grow = block_row + ty * 8 + i;
        if (grow < M) {
#pragma unroll
            for (int j = 0; j < 8; j += 4) {
                *(float4*)&C[(size_t)grow * NHID + tx * 8 + j] =
                    make_float4(acc[i][j], acc[i][j+1], acc[i][j+2], acc[i][j+3]);
            }
        }
    }
}

// ---------------------------------------------------------------------------
// Bias-broadcast initializers (accumulators start at the bias)
// ---------------------------------------------------------------------------
__global__ void init_bias128_kernel(float* __restrict__ dst,
                                    const float* __restrict__ b)
{
    __shared__ float sb[NHID];
    if (threadIdx.x < NHID) sb[threadIdx.x] = b[threadIdx.x];
    __syncthreads();
    size_t idx = (size_t)blockIdx.x * blockDim.x + threadIdx.x;
    size_t total = (size_t)N_NODES * NHID;
    if (idx < total) dst[idx] = sb[idx & (NHID - 1)];
}

__global__ void init_bias40_kernel(float* __restrict__ dst,
                                   const float* __restrict__ b)
{
    __shared__ float sb[NCLASS];
    if (threadIdx.x < NCLASS) sb[threadIdx.x] = b[threadIdx.x];
    __syncthreads();
    size_t idx = (size_t)blockIdx.x * blockDim.x + threadIdx.x;
    size_t total = (size_t)N_NODES * NCLASS;
    if (idx < total) dst[idx] = dst == nullptr ? 0.f : sb[idx % NCLASS];
}

// ---------------------------------------------------------------------------
// SpMM layer 1: one warp per edge, 32 lanes x float4 = full 128-float row.
// Gather from g_h1 (L2-resident), scale by edge weight, vector-reduce into
// g_agg1 via red.global.add.v4.f32 (no return -> max L2 reduction tput).
// ---------------------------------------------------------------------------
__device__ __forceinline__ void red_add_v4(float* addr, float4 v)
{
    asm volatile("red.global.add.v4.f32 [%0], {%1, %2, %3, %4};"
                 :: "l"(addr), "f"(v.x), "f"(v.y), "f"(v.z), "f"(v.w)
                 : "memory");
}

__global__ __launch_bounds__(256) void spmm1_kernel(
    const int* __restrict__ esrc, const int* __restrict__ edst,
    const float* __restrict__ ew)
{
    unsigned gid  = blockIdx.x * blockDim.x + threadIdx.x;
    unsigned e    = gid >> 5;
    unsigned lane = gid & 31;
    if (e >= N_EDGES) return;
    int src = esrc[e];
    int dst = edst[e];
    float w = ew[e];
    float4 v = *(const float4*)&g_h1[(size_t)src * NHID + lane * 4];
    v.x *= w; v.y *= w; v.z *= w; v.w *= w;
    red_add_v4(&g_agg1[(size_t)dst * NHID + lane * 4], v);
}

// ---------------------------------------------------------------------------
// GEMM2: C[M,40] = relu(H[M,128]) @ W2[128,40]. W2 + 32 H-rows staged in smem.
// ---------------------------------------------------------------------------
__global__ __launch_bounds__(256) void gemm2_kernel(
    const float* __restrict__ H, const float* __restrict__ W2,
    float* __restrict__ C, int M)
{
    __shared__ float sW[NHID * NCLASS];   // 20 KB
    __shared__ float sh[32 * NHID];       // 16 KB

    const int n0 = blockIdx.x * 32;

    // Load W2 (5120 floats = 1280 float4)
    for (int i = threadIdx.x; i < (NHID * NCLASS) / 4; i += 256)
        *(float4*)&sW[i * 4] = *(const float4*)&W2[i * 4];

    // Load 32 H rows with fused ReLU (4096 floats = 1024 float4)
    for (int i = threadIdx.x; i < (32 * NHID) / 4; i += 256) {
        int r = (i * 4) / NHID;
        float4 v = make_float4(0.f, 0.f, 0.f, 0.f);
        if (n0 + r < M) {
            v = *(const float4*)&H[(size_t)(n0 + r) * NHID + ((i * 4) & (NHID - 1))];
            v.x = fmaxf(v.x, 0.f); v.y = fmaxf(v.y, 0.f);
            v.z = fmaxf(v.z, 0.f); v.w = fmaxf(v.w, 0.f);
        }
        *(float4*)&sh[i * 4] = v;
    }
    __syncthreads();

    // 32*40 = 1280 outputs, 5 per thread
#pragma unroll
    for (int it = 0; it < 5; it++) {
        int o = threadIdx.x + it * 256;
        int node = o / NCLASS;
        int c    = o % NCLASS;
        float sum = 0.f;
#pragma unroll
        for (int k = 0; k < NHID; k++)
            sum += sh[node * NHID + k] * sW[k * NCLASS + c];
        if (n0 + node < M) C[(size_t)(n0 + node) * NCLASS + c] = sum;
    }
}

// ---------------------------------------------------------------------------
// SpMM layer 2: F=40 -> 10 float4 chunks per edge; one thread per (edge,chunk)
// ---------------------------------------------------------------------------
__global__ __launch_bounds__(256) void spmm2_kernel(
    const int* __restrict__ esrc, const int* __restrict__ edst,
    const float* __restrict__ ew, float* __restrict__ out)
{
    unsigned gid = blockIdx.x * blockDim.x + threadIdx.x;
    unsigned e   = gid / 10;
    unsigned c   = gid % 10;
    if (e >= N_EDGES) return;
    int src = esrc[e];
    int dst = edst[e];
    float w = ew[e];
    float4 v = *(const float4*)&g_h2[(size_t)src * NCLASS + c * 4];
    v.x *= w; v.y *= w; v.z *= w; v.w *= w;
    red_add_v4(&out[(size_t)dst * NCLASS + c * 4], v);
}

// ---------------------------------------------------------------------------
// kernel_launch
// inputs: 0=x 1=edge_src 2=edge_dst 3=edge_weight 4=W1 5=b1 6=W2 7=b2
// ---------------------------------------------------------------------------
extern "C" void kernel_launch(void* const* d_in, const int* in_sizes, int n_in,
                              void* d_out, int out_size)
{
    const float* x   = (const float*)d_in[0];
    const int*   es  = (const int*)d_in[1];
    const int*   ed  = (const int*)d_in[2];
    const float* ew  = (const float*)d_in[3];
    const float* W1  = (const float*)d_in[4];
    const float* b1  = (const float*)d_in[5];
    const float* W2  = (const float*)d_in[6];
    const float* b2  = (const float*)d_in[7];
    float* out = (float*)d_out;

    float *h1, *agg1, *h2;
    cudaGetSymbolAddress((void**)&h1,   g_h1);
    cudaGetSymbolAddress((void**)&agg1, g_agg1);
    cudaGetSymbolAddress((void**)&h2,   g_h2);

    const int M = N_NODES;

    // 1) support1 = x @ W1
    gemm1_kernel<<<(M + 127) / 128, 256>>>(x, W1, h1, M);

    // 2) agg1 = b1 (broadcast)
    {
        size_t total = (size_t)M * NHID;
        init_bias128_kernel<<<(unsigned)((total + 255) / 256), 256>>>(agg1, b1);
    }

    // 3) agg1 += scatter-add of weighted gathers (warp per edge)
    {
        size_t threads = (size_t)N_EDGES * 32;
        spmm1_kernel<<<(unsigned)((threads + 255) / 256), 256>>>(es, ed, ew);
    }

    // 4) support2 = relu(agg1) @ W2
    gemm2_kernel<<<(M + 31) / 32, 256>>>(agg1, W2, h2, M);

    // 5) out = b2 (broadcast)
    {
        size_t total = (size_t)M * NCLASS;
        init_bias40_kernel<<<(unsigned)((total + 255) / 256), 256>>>(out, b2);
    }

    // 6) out += scatter-add layer 2
    {
        size_t threads = (size_t)N_EDGES * 10;
        spmm2_kernel<<<(unsigned)((threads + 255) / 256), 256>>>(es, ed, ew, out);
    }
}

// round 7
// speedup vs baseline: 1.3304x; 1.3304x over previous
#include <cuda_runtime.h>
#include <cuda_bf16.h>
#include <cstdint>

// Problem constants (fixed by the reference)
#define N_NODES 50000
#define N_EDGES 800000
#define NFEAT   512
#define NHID    128
#define NCLASS  40

// Device scratch (no cudaMalloc allowed)
__device__ float g_h1[N_NODES * NHID];    // support1 = x @ W1      (25.6 MB)
__device__ float g_agg1[N_NODES * NHID];  // aggregated layer-1 out (25.6 MB)
__device__ float g_h2[N_NODES * NCLASS];  // support2 = relu(h) @ W2 (8 MB)

__device__ __forceinline__ uint32_t cvt_tf32(float f) {
    uint32_t out;
    asm("cvt.rna.tf32.f32 %0, %1;" : "=r"(out) : "f"(f));
    return out;
}

__device__ __forceinline__ void mma_tf32(
    float& d0, float& d1, float& d2, float& d3,
    uint32_t a0, uint32_t a1, uint32_t a2, uint32_t a3,
    uint32_t b0, uint32_t b1)
{
    asm volatile(
        "mma.sync.aligned.m16n8k8.row.col.f32.tf32.tf32.f32 "
        "{%0,%1,%2,%3}, {%4,%5,%6,%7}, {%8,%9}, {%0,%1,%2,%3};"
        : "+f"(d0), "+f"(d1), "+f"(d2), "+f"(d3)
        : "r"(a0), "r"(a1), "r"(a2), "r"(a3), "r"(b0), "r"(b1));
}

// ===========================================================================
// GEMM1 (HMMA tf32): C[M,128] = tf32(A[M,512]) @ tf32(W1[512,128])
// CTA tile 128x128, BK=32, 256 threads = 8 warps, warp tile 32(M) x 64(N).
// smem holds frag-permuted tiles so the inner loop is pure LDS.128:
//   sA[ks][mt][lane][slot]  : slot = a0..a3 of m16k8 frag  (one LDS.128/frag)
//   sB[ks][ntp][lane][slot] : slot = {b0,b1}(nt even),{b0,b1}(nt odd)
// ===========================================================================
#define G1_BK 32

__global__ __launch_bounds__(256) void gemm1_mma_kernel(
    const float* __restrict__ A, const float* __restrict__ W1,
    float* __restrict__ C, int M)
{
    __shared__ uint32_t sA[4 * 8 * 32 * 4];   // 16 KB  [ks][mt][lane][slot]
    __shared__ uint32_t sB[4 * 8 * 32 * 4];   // 16 KB  [ks][ntp][lane][slot]

    const int tid  = threadIdx.x;
    const int lane = tid & 31;
    const int wid  = tid >> 5;
    const int warp_m = wid & 3;        // 4 M-groups of 32 rows
    const int warp_n = wid >> 2;       // 2 N-groups of 64 cols
    const int m0 = blockIdx.x * 128;

    float acc[2][8][4];
#pragma unroll
    for (int mi = 0; mi < 2; mi++)
#pragma unroll
        for (int nt = 0; nt < 8; nt++)
#pragma unroll
            for (int j = 0; j < 4; j++) acc[mi][nt][j] = 0.0f;

    for (int k0 = 0; k0 < NFEAT; k0 += G1_BK) {
        // ---- stage A: 128 rows x 32 k (1024 float4, 4 per thread) ----
#pragma unroll
        for (int t = 0; t < 4; t++) {
            int i = tid + t * 256;
            int r = i >> 3;                 // row 0..127
            int q = i & 7;                  // float4 index in k (kk = q*4+j)
            float4 v = make_float4(0.f, 0.f, 0.f, 0.f);
            if (m0 + r < M)
                v = *(const float4*)&A[(size_t)(m0 + r) * NFEAT + k0 + q * 4];
            uint32_t u[4] = {cvt_tf32(v.x), cvt_tf32(v.y), cvt_tf32(v.z), cvt_tf32(v.w)};
            int ks   = q >> 1;
            int mt   = r >> 4;
            int slot = ((r >> 3) & 1) + 2 * (q & 1);
            int base = ((ks * 8 + mt) * 32 + (r & 7) * 4) * 4 + slot;
#pragma unroll
            for (int j = 0; j < 4; j++) sA[base + j * 4] = u[j];
        }
        // ---- stage B: 32 k x 128 n from W1 (1024 float4) ----
#pragma unroll
        for (int t = 0; t < 4; t++) {
            int i = tid + t * 256;
            int kk = i >> 5;                // 0..31
            int nf = i & 31;                // n = nf*4 + j
            float4 v = *(const float4*)&W1[(size_t)(k0 + kk) * NHID + nf * 4];
            uint32_t u[4] = {cvt_tf32(v.x), cvt_tf32(v.y), cvt_tf32(v.z), cvt_tf32(v.w)};
            int ks   = kk >> 3;
            int kc   = kk & 7;
            int ntp  = nf >> 2;
            int slot = ((nf >> 1) & 1) * 2 + (kc >> 2);
            int base = ((ks * 8 + ntp) * 32 + (nf & 1) * 16 + (kc & 3)) * 4 + slot;
#pragma unroll
            for (int j = 0; j < 4; j++) sB[base + j * 16] = u[j];
        }
        __syncthreads();

        // ---- compute: 4 k-steps of K=8 ----
#pragma unroll
        for (int ks = 0; ks < 4; ks++) {
            uint4 af[2];
#pragma unroll
            for (int mi = 0; mi < 2; mi++) {
                int mt = warp_m * 2 + mi;
                af[mi] = *(const uint4*)&sA[((ks * 8 + mt) * 32 + lane) * 4];
            }
#pragma unroll
            for (int np = 0; np < 4; np++) {
                int ntp = warp_n * 4 + np;
                uint4 bf = *(const uint4*)&sB[((ks * 8 + ntp) * 32 + lane) * 4];
#pragma unroll
                for (int mi = 0; mi < 2; mi++) {
                    mma_tf32(acc[mi][np*2][0], acc[mi][np*2][1],
                             acc[mi][np*2][2], acc[mi][np*2][3],
                             af[mi].x, af[mi].y, af[mi].z, af[mi].w,
                             bf.x, bf.y);
                    mma_tf32(acc[mi][np*2+1][0], acc[mi][np*2+1][1],
                             acc[mi][np*2+1][2], acc[mi][np*2+1][3],
                             af[mi].x, af[mi].y, af[mi].z, af[mi].w,
                             bf.z, bf.w);
                }
            }
        }
        __syncthreads();
    }

    // ---- epilogue: D frag (m16n8): d0 (r=l>>2, c=(l&3)*2), d1 c+1, d2/d3 r+8
#pragma unroll
    for (int mi = 0; mi < 2; mi++) {
        int r_base = m0 + warp_m * 32 + mi * 16 + (lane >> 2);
#pragma unroll
        for (int nt = 0; nt < 8; nt++) {
            int col = warp_n * 64 + nt * 8 + (lane & 3) * 2;
            if (r_base < M)
                *(float2*)&C[(size_t)r_base * NHID + col] =
                    make_float2(acc[mi][nt][0], acc[mi][nt][1]);
            if (r_base + 8 < M)
                *(float2*)&C[(size_t)(r_base + 8) * NHID + col] =
                    make_float2(acc[mi][nt][2], acc[mi][nt][3]);
        }
    }
}

// ---------------------------------------------------------------------------
// Bias-broadcast initializers (accumulators start at the bias)
// ---------------------------------------------------------------------------
__global__ void init_bias128_kernel(float* __restrict__ dst,
                                    const float* __restrict__ b)
{
    __shared__ float sb[NHID];
    if (threadIdx.x < NHID) sb[threadIdx.x] = b[threadIdx.x];
    __syncthreads();
    size_t idx = (size_t)blockIdx.x * blockDim.x + threadIdx.x;
    size_t total = (size_t)N_NODES * NHID;
    if (idx < total) dst[idx] = sb[idx & (NHID - 1)];
}

__global__ void init_bias40_kernel(float* __restrict__ dst,
                                   const float* __restrict__ b)
{
    __shared__ float sb[NCLASS];
    if (threadIdx.x < NCLASS) sb[threadIdx.x] = b[threadIdx.x];
    __syncthreads();
    size_t idx = (size_t)blockIdx.x * blockDim.x + threadIdx.x;
    size_t total = (size_t)N_NODES * NCLASS;
    if (idx < total) dst[idx] = sb[idx % NCLASS];
}

// ---------------------------------------------------------------------------
// SpMM layer 1: one warp per edge; red.global.add.v4.f32 scatter
// ---------------------------------------------------------------------------
__device__ __forceinline__ void red_add_v4(float* addr, float4 v)
{
    asm volatile("red.global.add.v4.f32 [%0], {%1, %2, %3, %4};"
                 :: "l"(addr), "f"(v.x), "f"(v.y), "f"(v.z), "f"(v.w)
                 : "memory");
}

__global__ __launch_bounds__(256) void spmm1_kernel(
    const int* __restrict__ esrc, const int* __restrict__ edst,
    const float* __restrict__ ew)
{
    unsigned gid  = blockIdx.x * blockDim.x + threadIdx.x;
    unsigned e    = gid >> 5;
    unsigned lane = gid & 31;
    if (e >= N_EDGES) return;
    int src = esrc[e];
    int dst = edst[e];
    float w = ew[e];
    float4 v = *(const float4*)&g_h1[(size_t)src * NHID + lane * 4];
    v.x *= w; v.y *= w; v.z *= w; v.w *= w;
    red_add_v4(&g_agg1[(size_t)dst * NHID + lane * 4], v);
}

// ---------------------------------------------------------------------------
// GEMM2: C[M,40] = relu(H[M,128]) @ W2[128,40]
// Thread tile: 4 nodes x 5 classes. sh staged [k][node] (transposed).
// ---------------------------------------------------------------------------
__global__ __launch_bounds__(256) void gemm2_kernel(
    const float* __restrict__ H, const float* __restrict__ W2,
    float* __restrict__ C, int M)
{
    __shared__ float sW[NHID * NCLASS];   // [k][c]  20 KB
    __shared__ float sh[32 * 128];        // [k][node] 16 KB

    const int tid = threadIdx.x;
    const int tx = tid & 7;               // class group: c = tx + j*8
    const int ty = tid >> 3;              // node group: nodes ty*4 .. ty*4+3
    const int n0 = blockIdx.x * 128;

    for (int i = tid; i < (NHID * NCLASS) / 4; i += 256)
        *(float4*)&sW[i * 4] = *(const float4*)&W2[i * 4];

    float acc[4][5];
#pragma unroll
    for (int i = 0; i < 4; i++)
#pragma unroll
        for (int j = 0; j < 5; j++) acc[i][j] = 0.0f;

    for (int kc = 0; kc < 4; kc++) {
        __syncthreads();
        // stage 32 k x 128 nodes, transposed, with ReLU
        for (int i = tid; i < 1024; i += 256) {
            int node = i & 127;
            int kq   = i >> 7;            // 0..7 (float4 chunks of k)
            float4 v = make_float4(0.f, 0.f, 0.f, 0.f);
            if (n0 + node < M) {
                v = *(const float4*)&H[(size_t)(n0 + node) * NHID + kc * 32 + kq * 4];
                v.x = fmaxf(v.x, 0.f); v.y = fmaxf(v.y, 0.f);
                v.z = fmaxf(v.z, 0.f); v.w = fmaxf(v.w, 0.f);
            }
            sh[(kq * 4 + 0) * 128 + node] = v.x;
            sh[(kq * 4 + 1) * 128 + node] = v.y;
            sh[(kq * 4 + 2) * 128 + node] = v.z;
            sh[(kq * 4 + 3) * 128 + node] = v.w;
        }
        __syncthreads();

#pragma unroll
        for (int k = 0; k < 32; k++) {
            float4 h4 = *(const float4*)&sh[k * 128 + ty * 4];
            const float* wr = &sW[(kc * 32 + k) * NCLASS + tx];
#pragma unroll
            for (int j = 0; j < 5; j++) {
                float w = wr[j * 8];
                acc[0][j] += h4.x * w;
                acc[1][j] += h4.y * w;
                acc[2][j] += h4.z * w;
                acc[3][j] += h4.w * w;
            }
        }
    }

#pragma unroll
    for (int i = 0; i < 4; i++) {
        int node = n0 + ty * 4 + i;
        if (node < M) {
#pragma unroll
            for (int j = 0; j < 5; j++)
                C[(size_t)node * NCLASS + tx + j * 8] = acc[i][j];
        }
    }
}

// ---------------------------------------------------------------------------
// SpMM layer 2: F=40 -> 10 float4 chunks per edge
// ---------------------------------------------------------------------------
__global__ __launch_bounds__(256) void spmm2_kernel(
    const int* __restrict__ esrc, const int* __restrict__ edst,
    const float* __restrict__ ew, float* __restrict__ out)
{
    unsigned gid = blockIdx.x * blockDim.x + threadIdx.x;
    unsigned e   = gid / 10;
    unsigned c   = gid % 10;
    if (e >= N_EDGES) return;
    int src = esrc[e];
    int dst = edst[e];
    float w = ew[e];
    float4 v = *(const float4*)&g_h2[(size_t)src * NCLASS + c * 4];
    v.x *= w; v.y *= w; v.z *= w; v.w *= w;
    red_add_v4(&out[(size_t)dst * NCLASS + c * 4], v);
}

// ---------------------------------------------------------------------------
// kernel_launch
// inputs: 0=x 1=edge_src 2=edge_dst 3=edge_weight 4=W1 5=b1 6=W2 7=b2
// ---------------------------------------------------------------------------
extern "C" void kernel_launch(void* const* d_in, const int* in_sizes, int n_in,
                              void* d_out, int out_size)
{
    const float* x   = (const float*)d_in[0];
    const int*   es  = (const int*)d_in[1];
    const int*   ed  = (const int*)d_in[2];
    const float* ew  = (const float*)d_in[3];
    const float* W1  = (const float*)d_in[4];
    const float* b1  = (const float*)d_in[5];
    const float* W2  = (const float*)d_in[6];
    const float* b2  = (const float*)d_in[7];
    float* out = (float*)d_out;

    float *h1, *agg1, *h2;
    cudaGetSymbolAddress((void**)&h1,   g_h1);
    cudaGetSymbolAddress((void**)&agg1, g_agg1);
    cudaGetSymbolAddress((void**)&h2,   g_h2);

    const int M = N_NODES;

    // 1) support1 = x @ W1  (tf32 HMMA)
    gemm1_mma_kernel<<<(M + 127) / 128, 256>>>(x, W1, h1, M);

    // 2) agg1 = b1 (broadcast)
    {
        size_t total = (size_t)M * NHID;
        init_bias128_kernel<<<(unsigned)((total + 255) / 256), 256>>>(agg1, b1);
    }

    // 3) agg1 += scatter-add of weighted gathers (warp per edge)
    {
        size_t threads = (size_t)N_EDGES * 32;
        spmm1_kernel<<<(unsigned)((threads + 255) / 256), 256>>>(es, ed, ew);
    }

    // 4) support2 = relu(agg1) @ W2
    gemm2_kernel<<<(M + 127) / 128, 256>>>(agg1, W2, h2, M);

    // 5) out = b2 (broadcast)
    {
        size_t total = (size_t)M * NCLASS;
        init_bias40_kernel<<<(unsigned)((total + 255) / 256), 256>>>(out, b2);
    }

    // 6) out += scatter-add layer 2
    {
        size_t threads = (size_t)N_EDGES * 10;
        spmm2_kernel<<<(unsigned)((threads + 255) / 256), 256>>>(es, ed, ew, out);
    }
}